// round 2
// baseline (speedup 1.0000x reference)
#include <cuda_runtime.h>
#include <math.h>
#include <stdint.h>

// Problem dims (fixed by the dataset)
#define NT 2048      // time steps
#define NB 64        // batch
#define NI 256       // input size
#define NH 512       // hidden size
#define NG 2048      // 4*NH gate columns
#define GRID_B 128   // persistent CTAs (1 per SM, < 148 -> single wave, co-resident)

// Scratch (allocation-free rule: __device__ globals)
__device__ float g_xw[(size_t)NT * NB * NG];   // 1 GiB: precomputed x@Wi + B, [t][b][gatecol]
__device__ float g_h[2 * NH * NB];             // double-buffered h, transposed [k][b]
__device__ unsigned g_bar_count;
__device__ unsigned g_bar_gen;

__device__ __forceinline__ float sigmoidf_(float x) { return 1.0f / (1.0f + expf(-x)); }

// ---- packed f32x2 helpers (Blackwell FFMA2: 2 fp32 FMAs / instruction) ----
__device__ __forceinline__ unsigned long long pack2(float x, float y) {
    unsigned long long r;
    asm("mov.b64 %0, {%1, %2};" : "=l"(r) : "f"(x), "f"(y));
    return r;
}
__device__ __forceinline__ unsigned long long fma2(unsigned long long a,
                                                   unsigned long long b,
                                                   unsigned long long c) {
    unsigned long long d;
    asm("fma.rn.f32x2 %0, %1, %2, %3;" : "=l"(d) : "l"(a), "l"(b), "l"(c));
    return d;
}
__device__ __forceinline__ float2 unpack2(unsigned long long v) {
    float2 f;
    asm("mov.b64 {%0, %1}, %2;" : "=f"(f.x), "=f"(f.y) : "l"(v));
    return f;
}

// Software grid barrier across GRID_B co-resident CTAs.
__device__ __forceinline__ void grid_barrier() {
    __syncthreads();
    if (threadIdx.x == 0) {
        volatile unsigned* genp = &g_bar_gen;
        unsigned my = *genp;
        __threadfence();                       // release: publish h writes
        if (atomicAdd(&g_bar_count, 1u) == GRID_B - 1) {
            atomicExch(&g_bar_count, 0u);
            __threadfence();
            *genp = my + 1;
        } else {
            while (*genp == my) { __nanosleep(32); }
        }
        __threadfence();                       // acquire
    }
    __syncthreads();
}

// ---------------- Phase 1: xW = x @ Wi + B  (fp32 tiled GEMM, FFMA2 core) ----------------
// M=131072 (t*64+b), K=256, N=2048. 128x128 tile, BK=8, 256 threads, 8x8 microtile.
__global__ void __launch_bounds__(256, 2)
xw_gemm_kernel(const float* __restrict__ x, const float* __restrict__ Wi,
               const float* __restrict__ bias) {
    __shared__ __align__(16) float As[8][132];   // +4 pad: conflict-free transpose store
    __shared__ __align__(16) float Bs[8][128];

    const int tid = threadIdx.x;
    const int tx = tid & 15, ty = tid >> 4;
    const int bm = blockIdx.y << 7, bn = blockIdx.x << 7;
    const int lrow = tid >> 1, lk = (tid & 1) << 2;        // A tile loader
    const int brow = tid >> 5, bcol = (tid & 31) << 2;     // B tile loader

    unsigned long long acc2[8][4];
    #pragma unroll
    for (int i = 0; i < 8; i++)
        #pragma unroll
        for (int j = 0; j < 4; j++) acc2[i][j] = 0ull;

    for (int kt = 0; kt < NI; kt += 8) {
        float4 av = *reinterpret_cast<const float4*>(x + (size_t)(bm + lrow) * NI + kt + lk);
        float4 bv = *reinterpret_cast<const float4*>(Wi + (size_t)(kt + brow) * NG + bn + bcol);
        As[lk + 0][lrow] = av.x;
        As[lk + 1][lrow] = av.y;
        As[lk + 2][lrow] = av.z;
        As[lk + 3][lrow] = av.w;
        *reinterpret_cast<float4*>(&Bs[brow][bcol]) = bv;
        __syncthreads();
        #pragma unroll
        for (int kk = 0; kk < 8; kk++) {
            float4 t0 = *reinterpret_cast<const float4*>(&As[kk][ty << 3]);
            float4 t1 = *reinterpret_cast<const float4*>(&As[kk][(ty << 3) + 4]);
            const ulonglong2* brow2 = reinterpret_cast<const ulonglong2*>(&Bs[kk][tx << 3]);
            ulonglong2 bv0 = brow2[0], bv1 = brow2[1];
            unsigned long long b2[4] = {bv0.x, bv0.y, bv1.x, bv1.y};
            float a[8] = {t0.x, t0.y, t0.z, t0.w, t1.x, t1.y, t1.z, t1.w};
            #pragma unroll
            for (int i = 0; i < 8; i++) {
                unsigned long long ap = pack2(a[i], a[i]);
                #pragma unroll
                for (int j = 0; j < 4; j++)
                    acc2[i][j] = fma2(ap, b2[j], acc2[i][j]);
            }
        }
        __syncthreads();
    }

    float4 bb0 = *reinterpret_cast<const float4*>(bias + bn + (tx << 3));
    float4 bb1 = *reinterpret_cast<const float4*>(bias + bn + (tx << 3) + 4);
    const float bb[8] = {bb0.x, bb0.y, bb0.z, bb0.w, bb1.x, bb1.y, bb1.z, bb1.w};
    #pragma unroll
    for (int i = 0; i < 8; i++) {
        size_t row = (size_t)bm + (ty << 3) + i;
        float o[8];
        #pragma unroll
        for (int j = 0; j < 4; j++) {
            float2 v = unpack2(acc2[i][j]);
            o[2 * j] = v.x + bb[2 * j];
            o[2 * j + 1] = v.y + bb[2 * j + 1];
        }
        *reinterpret_cast<float4*>(g_xw + row * NG + bn + (tx << 3)) =
            make_float4(o[0], o[1], o[2], o[3]);
        *reinterpret_cast<float4*>(g_xw + row * NG + bn + (tx << 3) + 4) =
            make_float4(o[4], o[5], o[6], o[7]);
    }
}

// ---------------- Phase 2: persistent recurrent kernel ----------------
// 128 CTAs x 512 threads (16 warps/SM). CTA owns 4 hidden units = 16 gate cols.
// Per step: stage h[512][64] + xW tile into SMEM, split-K(8) x (8 col-pairs) x
// (8 batch-grp) FFMA2 partials, SMEM reduce + xW add, LSTM cell (c in regs).
#define SMEM_B_FLOATS (NH * 16 + NH * NB + 8 * 1024 + 16 * 64 + 16 * 64)  // 201728 B

__global__ void __launch_bounds__(512, 1)
lstm_rec_kernel(const float* __restrict__ Wh, float* __restrict__ out, int write_state) {
    extern __shared__ float smem[];
    float* sWh   = smem;                  // [512][16]  Wh slice, resident all steps
    float* shT   = sWh + NH * 16;         // [512][64]  h (k-major)
    float* sRed  = shT + NH * NB;         // [8][1024]  split-K partials
    float* sGate = sRed + 8 * 1024;       // [16][64]   reduced gates
    float* sXW   = sGate + 16 * 64;       // [64][16]   xW tile for this step

    const int tid = threadIdx.x;
    const int u_base = blockIdx.x << 2;

    // Load this CTA's Wh columns once (stays in SMEM for all 2048 steps).
    for (int idx = tid; idx < NH * 16; idx += 512) {
        int k = idx >> 4, c = idx & 15;
        int col = ((c >> 2) * NH) + u_base + (c & 3);
        sWh[idx] = Wh[(size_t)k * NG + col];
    }
    // Zero h buffer 0 (h_0 = 0); each CTA zeros its own 4 rows.
    if (tid < 256) {
        int i = tid >> 6, b = tid & 63;
        g_h[(u_base + i) * NB + b] = 0.f;
    }
    __threadfence();
    grid_barrier();

    const int bg = tid & 7;                // batch group (8 batches)
    const int cg = (tid >> 3) & 7;         // column-pair group (2 cols)
    const int s  = tid >> 6;               // split-K slice (64 k's)
    const int eb = tid >> 2, ei = tid & 3; // epilogue (batch, unit), tid<256
    float c_reg = 0.f;

    const float2* sWh2 = reinterpret_cast<const float2*>(sWh);
    const ulonglong2* shT8 = reinterpret_cast<const ulonglong2*>(shT);
    unsigned long long* sRedU = reinterpret_cast<unsigned long long*>(sRed);

    for (int t = 0; t < NT; t++) {
        // Stage h (read buffer t&1) from L2 (.cg for coherence) + xW tile.
        const float4* gh4 = reinterpret_cast<const float4*>(g_h + (t & 1) * (NH * NB));
        float4* shTw = reinterpret_cast<float4*>(shT);
        #pragma unroll
        for (int j = 0; j < 16; j++)
            shTw[tid + (j << 9)] = __ldcg(gh4 + tid + (j << 9));
        if (tid < 256) {   // xW tile: [b][g][4 units] = 4KB, 16B coalesced chunks
            int b = tid >> 2, g = tid & 3;
            reinterpret_cast<float4*>(sXW)[tid] = __ldg(reinterpret_cast<const float4*>(
                g_xw + (size_t)t * (NB * NG) + (size_t)b * NG + g * NH + u_base));
        }
        __syncthreads();

        // Split-K FFMA2 partials: 2 cols x 8 batches (4 packed pairs) per thread.
        unsigned long long acc2[2][4];
        #pragma unroll
        for (int c = 0; c < 2; c++)
            #pragma unroll
            for (int p = 0; p < 4; p++) acc2[c][p] = 0ull;

        const int kbeg = s << 6;
        #pragma unroll 4
        for (int k = kbeg; k < kbeg + 64; k++) {
            float2 w = sWh2[(k << 3) + cg];
            unsigned long long wp0 = pack2(w.x, w.x);
            unsigned long long wp1 = pack2(w.y, w.y);
            ulonglong2 h0 = shT8[(k << 4) + (bg << 1)];
            ulonglong2 h1 = shT8[(k << 4) + (bg << 1) + 1];
            acc2[0][0] = fma2(wp0, h0.x, acc2[0][0]);
            acc2[0][1] = fma2(wp0, h0.y, acc2[0][1]);
            acc2[0][2] = fma2(wp0, h1.x, acc2[0][2]);
            acc2[0][3] = fma2(wp0, h1.y, acc2[0][3]);
            acc2[1][0] = fma2(wp1, h0.x, acc2[1][0]);
            acc2[1][1] = fma2(wp1, h0.y, acc2[1][1]);
            acc2[1][2] = fma2(wp1, h1.x, acc2[1][2]);
            acc2[1][3] = fma2(wp1, h1.y, acc2[1][3]);
        }
        #pragma unroll
        for (int c = 0; c < 2; c++)
            #pragma unroll
            for (int p = 0; p < 4; p++)
                sRedU[(s << 9) + ((2 * cg + c) << 5) + (bg << 2) + p] = acc2[c][p];
        __syncthreads();

        // Reduce 8 partials + add xW -> sGate (2 gate values per thread)
        {
            float2 sum = reinterpret_cast<const float2*>(sRed)[tid];
            #pragma unroll
            for (int ss = 1; ss < 8; ss++) {
                float2 v = reinterpret_cast<const float2*>(sRed)[(ss << 9) + tid];
                sum.x += v.x; sum.y += v.y;
            }
            const int c_idx = tid >> 5;
            const int b0 = (tid & 31) << 1;
            sum.x += sXW[b0 * 16 + c_idx];
            sum.y += sXW[(b0 + 1) * 16 + c_idx];
            reinterpret_cast<float2*>(sGate)[tid] = sum;
        }
        __syncthreads();

        // LSTM cell: thread <-> (batch eb, unit ei), c lives in a register.
        if (tid < 256) {
            float G0 = sGate[((0 * 4 + ei) << 6) + eb];
            float G1 = sGate[((1 * 4 + ei) << 6) + eb];
            float G2 = sGate[((2 * 4 + ei) << 6) + eb];
            float G3 = sGate[((3 * 4 + ei) << 6) + eb];
            float ig = sigmoidf_(G0);
            float fg = sigmoidf_(G1);
            float gg = tanhf(G2);
            float og = sigmoidf_(G3);
            c_reg = fg * c_reg + ig * gg;
            float h = og * tanhf(c_reg);
            int u = u_base + ei;
            out[((size_t)t * NB + eb) * NH + u] = h;
            g_h[((t + 1) & 1) * (NH * NB) + u * NB + eb] = h;   // write buffer (t+1)&1
            if (write_state && t == NT - 1) {
                size_t base = (size_t)NT * NB * NH;
                out[base + (size_t)eb * NH + u] = h;                         // hT
                out[base + (size_t)NB * NH + (size_t)eb * NH + u] = c_reg;   // cT
            }
        }
        __threadfence();
        grid_barrier();
    }
}

extern "C" void kernel_launch(void* const* d_in, const int* in_sizes, int n_in,
                              void* d_out, int out_size) {
    const float* x  = (const float*)d_in[0];   // [T, BS, IN]
    const float* Wi = (const float*)d_in[1];   // [IN, 4H]
    const float* Wh = (const float*)d_in[2];   // [H, 4H]
    const float* B  = (const float*)d_in[3];   // [4H]
    float* out = (float*)d_out;

    const int smem_bytes = SMEM_B_FLOATS * (int)sizeof(float);
    cudaFuncSetAttribute(lstm_rec_kernel, cudaFuncAttributeMaxDynamicSharedMemorySize, smem_bytes);

    // Phase 1: xW = x @ Wi + B
    dim3 gA(NG / 128, (NT * NB) / 128);
    xw_gemm_kernel<<<gA, 256>>>(x, Wi, B);

    // Does the output buffer include (hT, cT) after out[T,BS,H]?
    const long long need_full = (long long)NT * NB * NH + 2LL * NB * NH;
    int write_state = ((long long)out_size >= need_full) ? 1 : 0;

    // Phase 2: persistent recurrence
    lstm_rec_kernel<<<GRID_B, 512, smem_bytes>>>(Wh, out, write_state);
}